// round 11
// baseline (speedup 1.0000x reference)
#include <cuda_runtime.h>
#include <cuda_bf16.h>

using u32 = unsigned int;
using u64 = unsigned long long;

#define BPAIR 4096
#define NROWS 8192
#define DDIM  512
// exp(x/T) = 2^(x * 2*log2(e)),  T = 0.5
#define EXP_SCALE 2.8853900817779268f
#define LN2_F     0.6931471805599453f
#define NCTA 148

// ---------------- device scratch (no allocations allowed) ----------------
__device__ unsigned char g_nA[NROWS * DDIM];   // normalized [x1; z2], int8
__device__ unsigned char g_nB[NROWS * DDIM];   // normalized [x2; z1], int8
__device__ float g_scale[2 * NROWS];           // per-row dequant scale
__device__ float g_part[2 * 64 * NROWS];       // [mtx][slot 0..63][row] partials
__device__ float g_log_partial[128];
__device__ float g_pos_partial[NCTA];
__device__ unsigned int g_bar;                 // cumulative barrier counter
__device__ unsigned int g_done;                // last-block counter

// ---------------- PTX helpers ----------------
__device__ __forceinline__ u32 smem_u32(const void* p) {
    u32 a;
    asm("{ .reg .u64 t; cvta.to.shared.u64 t, %1; cvt.u32.u64 %0, t; }"
        : "=r"(a) : "l"(p));
    return a;
}
__device__ __forceinline__ float ex2f(float x) {
    float y; asm("ex2.approx.f32 %0, %1;" : "=f"(y) : "f"(x)); return y;
}
__device__ __forceinline__ float lg2f(float x) {
    float y; asm("lg2.approx.f32 %0, %1;" : "=f"(y) : "f"(x)); return y;
}
__device__ __forceinline__ void cp_async16(u32 dst, const void* src) {
    asm volatile("cp.async.cg.shared.global [%0], [%1], 16;"
                 :: "r"(dst), "l"(src) : "memory");
}
#define CP_COMMIT() asm volatile("cp.async.commit_group;" ::: "memory")
#define CP_WAIT0()  asm volatile("cp.async.wait_group 0;" ::: "memory")
#define CP_WAIT1()  asm volatile("cp.async.wait_group 1;" ::: "memory")
#define CP_WAIT2()  asm volatile("cp.async.wait_group 2;" ::: "memory")

__device__ __forceinline__ void ldsm4(u32 (&r)[4], u32 addr) {
    asm volatile("ldmatrix.sync.aligned.m8n8.x4.shared.b16 {%0,%1,%2,%3}, [%4];"
        : "=r"(r[0]), "=r"(r[1]), "=r"(r[2]), "=r"(r[3]) : "r"(addr));
}
// INT8 MMA, K=32, s32 accumulate.
__device__ __forceinline__ void mmai16832(int (&d)[4], const u32 (&a)[4],
                                          u32 b0, u32 b1) {
    asm volatile(
        "mma.sync.aligned.m16n8k32.row.col.s32.s8.s8.s32 "
        "{%0,%1,%2,%3}, {%4,%5,%6,%7}, {%8,%9}, {%0,%1,%2,%3};"
        : "+r"(d[0]), "+r"(d[1]), "+r"(d[2]), "+r"(d[3])
        : "r"(a[0]), "r"(a[1]), "r"(a[2]), "r"(a[3]), "r"(b0), "r"(b1));
}

__device__ __forceinline__ u32 pack_s8x4(float a, float b, float c, float d) {
    int ia = __float2int_rn(a), ib = __float2int_rn(b);
    int ic = __float2int_rn(c), id = __float2int_rn(d);
    return (u32)(ia & 0xFF) | ((u32)(ib & 0xFF) << 8) |
           ((u32)(ic & 0xFF) << 16) | ((u32)id << 24);
}

// Grid-wide barrier: cumulative target (148 for 1st use, 296 for 2nd).
// Release fence before arrive; acquire fence after observing the target.
__device__ __forceinline__ void grid_bar(unsigned int target) {
    __syncthreads();
    if (threadIdx.x == 0) {
        __threadfence();
        atomicAdd(&g_bar, 1u);
        volatile unsigned int* vb = &g_bar;
        while (*vb < target) {}
        __threadfence();
    }
    __syncthreads();
}

#define SMEM_BYTES 200704

// ---------------- fused persistent kernel: norm -> GEMM -> LSE -------------
__global__ void __launch_bounds__(256, 1) k_fused(
    const float* __restrict__ x1, const float* __restrict__ x2,
    const float* __restrict__ z1, const float* __restrict__ z2,
    float* __restrict__ out) {
    extern __shared__ char smem[];
    const int tid  = threadIdx.x;
    const int wid  = tid >> 5;
    const int lane = tid & 31;
    const int bx   = blockIdx.x;

    const u32 sb  = smem_u32(smem);
    float* rowred = (float*)smem;            // 256 floats
    float* colred = rowred + 256;            // 512 floats (header = 4096 B)
    const u32 A_base = sb + 4096u;           // 2 bufs x 4 chunks x 16KB
    const u32 B_base = A_base + 131072u;     // 4 slots x 16KB

    // ================= Phase 0: normalize + quantize + pair dots ==========
    {
        float posAcc = 0.f;
        for (int P = bx * 8 + wid; P < 2 * BPAIR; P += NCTA * 8) {
            int h = P >> 12;
            int i = P & (BPAIR - 1);
            const float* a = (h ? x2 : x1) + (size_t)i * DDIM;
            const float* b = (h ? z1 : z2) + (size_t)i * DDIM;
            unsigned char* matd = h ? g_nB : g_nA;

            float4 va[4], vb[4];
            float sd = 0.f, sa = 0.f, sbv = 0.f, ma = 0.f, mb = 0.f;
#pragma unroll
            for (int k = 0; k < 4; k++) {
                va[k] = ((const float4*)a)[lane + 32 * k];
                vb[k] = ((const float4*)b)[lane + 32 * k];
                sd += va[k].x * vb[k].x + va[k].y * vb[k].y + va[k].z * vb[k].z + va[k].w * vb[k].w;
                sa += va[k].x * va[k].x + va[k].y * va[k].y + va[k].z * va[k].z + va[k].w * va[k].w;
                sbv += vb[k].x * vb[k].x + vb[k].y * vb[k].y + vb[k].z * vb[k].z + vb[k].w * vb[k].w;
                ma = fmaxf(ma, fmaxf(fmaxf(fabsf(va[k].x), fabsf(va[k].y)),
                                     fmaxf(fabsf(va[k].z), fabsf(va[k].w))));
                mb = fmaxf(mb, fmaxf(fmaxf(fabsf(vb[k].x), fabsf(vb[k].y)),
                                     fmaxf(fabsf(vb[k].z), fabsf(vb[k].w))));
            }
#pragma unroll
            for (int o = 16; o; o >>= 1) {
                sd += __shfl_xor_sync(0xffffffffu, sd, o);
                sa += __shfl_xor_sync(0xffffffffu, sa, o);
                sbv += __shfl_xor_sync(0xffffffffu, sbv, o);
                ma = fmaxf(ma, __shfl_xor_sync(0xffffffffu, ma, o));
                mb = fmaxf(mb, __shfl_xor_sync(0xffffffffu, mb, o));
            }
            float ra = rsqrtf(sa), rb_ = rsqrtf(sbv);
            float qa = 127.f / ma, qb = 127.f / mb;
            u32* da = (u32*)(matd + (size_t)i * DDIM);
            u32* db = (u32*)(matd + (size_t)(BPAIR + i) * DDIM);
#pragma unroll
            for (int k = 0; k < 4; k++) {
                da[lane + 32 * k] = pack_s8x4(va[k].x * qa, va[k].y * qa,
                                              va[k].z * qa, va[k].w * qa);
                db[lane + 32 * k] = pack_s8x4(vb[k].x * qb, vb[k].y * qb,
                                              vb[k].z * qb, vb[k].w * qb);
            }
            if (lane == 0) {
                g_scale[h * NROWS + i]         = ma * ra * (1.f / 127.f);
                g_scale[h * NROWS + BPAIR + i] = mb * rb_ * (1.f / 127.f);
            }
            posAcc += sd * ra * rb_;
        }
        if (lane == 0) rowred[wid] = posAcc;
        __syncthreads();
        if (tid == 0) {
            float s = 0.f;
            for (int j = 0; j < 8; j++) s += rowred[j];
            g_pos_partial[bx] = s;
        }
    }
    grid_bar(NCTA);   // all quantized rows + scales visible

    // ================= Phase 1: symmetric sim GEMM (int8, triangle) =======
    {
        const int t0 = bx * 28 + (bx < 16 ? bx : 16);
        const int nT = 28 + (bx < 16 ? 1 : 0);
        const int totalChunks = nT * 4;

        int c_m = t0 / 2080;
        int rrem = t0 % 2080;
        int c_rb = 0;
        while (rrem >= 64 - c_rb) { rrem -= 64 - c_rb; c_rb++; }
        int c_jt = c_rb + rrem;

        int p_m = c_m, p_rb = c_rb, p_jt = c_jt, p_cc = 0, p_q = 0, p_ab = 0;
        bool p_attach = false;
        int ab = 0;

        const int warpM = wid >> 1, warpN = wid & 1;
        const int lx7 = lane & 7, l15 = lane & 15;
        const u32 aHi = (u32)(lane >> 4);
        const u32 bSegBit = (u32)((lane >> 3) & 1);
        const u32 aRowOff = (u32)(warpM * 32 + l15) * 128u;
        const u32 bRowOff = (u32)(warpN * 64 + lx7 + ((lane >> 4) << 3)) * 128u;
        const int qr = lane >> 2, qc = lane & 3;
        const int rowLo0 = warpM * 32 + qr;
        const int colB0  = warpN * 64 + qc * 2;

        // prologue: A block for first strip into buf 0 (group 0)
        {
            const unsigned char* mp = c_m ? g_nB : g_nA;
            const unsigned char* abase = mp + (size_t)(c_rb * 128) * DDIM;
#pragma unroll
            for (int t = 0; t < 16; t++) {
                int idx = tid + t * 256;
                int ch = idx >> 10, rem = idx & 1023, r = rem >> 3, sg = rem & 7;
                cp_async16(A_base + (u32)(ch * 16384 + r * 128 + ((sg ^ (r & 7)) << 4)),
                           abase + (size_t)r * DDIM + ch * 128 + sg * 16);
            }
            CP_COMMIT();
        }

        auto advancePF = [&]() {
            int orb = p_rb, om = p_m;
            p_jt++;
            if (p_jt == 64) { p_rb++; p_jt = p_rb; if (p_rb == 64) { p_m++; p_rb = 0; p_jt = 0; } }
            bool ns = (p_rb != orb) || (p_m != om);
            p_attach = ns;
            if (ns) p_ab ^= 1;
        };
        auto issuePF = [&]() {
            const unsigned char* mp = p_m ? g_nB : g_nA;
            u32 slot = B_base + (u32)(p_q & 3) * 16384u;
            const unsigned char* srcB = mp + (size_t)(p_jt * 128) * DDIM + p_cc * 128;
#pragma unroll
            for (int t = 0; t < 4; t++) {
                int idx = tid + t * 256;
                int r = idx >> 3, sg = idx & 7;
                cp_async16(slot + (u32)(r * 128 + ((sg ^ (r & 7)) << 4)),
                           srcB + (size_t)r * DDIM + sg * 16);
            }
            if (p_attach) {
                u32 dstA = A_base + (u32)p_ab * 65536u + (u32)p_cc * 16384u;
                const unsigned char* srcA = mp + (size_t)(p_rb * 128) * DDIM + p_cc * 128;
#pragma unroll
                for (int t = 0; t < 4; t++) {
                    int idx = tid + t * 256;
                    int r = idx >> 3, sg = idx & 7;
                    cp_async16(dstA + (u32)(r * 128 + ((sg ^ (r & 7)) << 4)),
                               srcA + (size_t)r * DDIM + sg * 16);
                }
            }
            CP_COMMIT();
            p_q++; p_cc++;
            if (p_cc == 4) { p_cc = 0; advancePF(); }
        };
        issuePF();
        issuePF();

        int acc0[2][8][4], acc1[2][8][4];
#pragma unroll
        for (int mi = 0; mi < 2; mi++)
#pragma unroll
            for (int ni = 0; ni < 8; ni++)
#pragma unroll
                for (int e = 0; e < 4; e++) { acc0[mi][ni][e] = 0; acc1[mi][ni][e] = 0; }

        float rsum[2][2], csum[8][2];
#pragma unroll
        for (int a2 = 0; a2 < 2; a2++) { rsum[a2][0] = 0.f; rsum[a2][1] = 0.f; }
#pragma unroll
        for (int ni = 0; ni < 8; ni++) { csum[ni][0] = 0.f; csum[ni][1] = 0.f; }

        int pv_m = 0, pv_rb = 0, pv_jt = 0;
        bool pv_dg = false, havePrev = false;

        auto epiSlice = [&](int (&accP)[2][8][4], int mi) {
            const float* gsc = g_scale + (size_t)pv_m * NROWS;
            float f0 = __ldg(gsc + pv_rb * 128 + rowLo0 + mi * 16) * EXP_SCALE;
            float f1 = __ldg(gsc + pv_rb * 128 + rowLo0 + mi * 16 + 8) * EXP_SCALE;
            const int rlo = rowLo0 + mi * 16, rhi = rlo + 8;
#pragma unroll
            for (int ni = 0; ni < 8; ni++) {
                float s0 = __ldg(gsc + pv_jt * 128 + colB0 + ni * 8);
                float s1 = __ldg(gsc + pv_jt * 128 + colB0 + ni * 8 + 1);
                const int colb = colB0 + ni * 8;
                float e0 = ex2f(__int2float_rn(accP[mi][ni][0]) * (f0 * s0));
                float e1 = ex2f(__int2float_rn(accP[mi][ni][1]) * (f0 * s1));
                float e2 = ex2f(__int2float_rn(accP[mi][ni][2]) * (f1 * s0));
                float e3 = ex2f(__int2float_rn(accP[mi][ni][3]) * (f1 * s1));
                if (pv_dg) {
                    if (colb     == rlo) e0 = 0.f;
                    if (colb + 1 == rlo) e1 = 0.f;
                    if (colb     == rhi) e2 = 0.f;
                    if (colb + 1 == rhi) e3 = 0.f;
                }
                rsum[mi][0] += e0 + e1;
                rsum[mi][1] += e2 + e3;
                csum[ni][0] += e0 + e2;
                csum[ni][1] += e1 + e3;
                accP[mi][ni][0] = 0; accP[mi][ni][1] = 0;
                accP[mi][ni][2] = 0; accP[mi][ni][3] = 0;
            }
        };

        auto epiReduce = [&]() {
            float* gpart = g_part + (size_t)pv_m * 64 * NROWS;
#pragma unroll
            for (int mi = 0; mi < 2; mi++)
#pragma unroll
                for (int h = 0; h < 2; h++) {
                    float v = rsum[mi][h];
                    v += __shfl_xor_sync(0xffffffffu, v, 1);
                    v += __shfl_xor_sync(0xffffffffu, v, 2);
                    if (qc == 0)
                        rowred[warpN * 128 + rowLo0 + mi * 16 + 8 * h] = v;
                }
#pragma unroll
            for (int ni = 0; ni < 8; ni++)
#pragma unroll
                for (int j = 0; j < 2; j++) {
                    float v = csum[ni][j];
                    v += __shfl_xor_sync(0xffffffffu, v, 4);
                    v += __shfl_xor_sync(0xffffffffu, v, 8);
                    v += __shfl_xor_sync(0xffffffffu, v, 16);
                    if (lane < 4)
                        colred[warpM * 128 + warpN * 64 + qc * 2 + ni * 8 + j] = v;
                }
            __syncthreads();
            if (tid < 128) {
                float rv = rowred[tid] + rowred[128 + tid];
                gpart[((size_t)pv_jt << 13) + pv_rb * 128 + tid] = rv;
                if (!pv_dg) {
                    float cv = colred[tid] + colred[128 + tid] +
                               colred[256 + tid] + colred[384 + tid];
                    gpart[((size_t)pv_rb << 13) + pv_jt * 128 + tid] = cv;
                }
            }
#pragma unroll
            for (int a2 = 0; a2 < 2; a2++) { rsum[a2][0] = 0.f; rsum[a2][1] = 0.f; }
#pragma unroll
            for (int ni = 0; ni < 8; ni++) { csum[ni][0] = 0.f; csum[ni][1] = 0.f; }
        };

        auto processTile = [&](int (&accC)[2][8][4], int (&accP)[2][8][4], int ti) {
            const bool dg = (c_jt == c_rb);
            const int myM = c_m, myRb = c_rb, myJt = c_jt;
#pragma unroll 1
            for (int cc = 0; cc < 4; cc++) {
                const int q = ti * 4 + cc;
                if (q + 2 < totalChunks) { issuePF(); CP_WAIT2(); }
                else if (q + 1 < totalChunks) { CP_WAIT1(); }
                else { CP_WAIT0(); }
                __syncthreads();

                const u32 aChunk = A_base + (u32)ab * 65536u + (u32)cc * 16384u + aRowOff;
                const u32 bBase  = B_base + (u32)(q & 3) * 16384u + bRowOff;
#pragma unroll
                for (int ks = 0; ks < 4; ks++) {
                    u32 A0[4], A1[4], B0[4], B1[4], B2[4], B3[4];
                    const u32 aoff = (((2u * ks + aHi) ^ (u32)lx7) << 4);
                    ldsm4(A0, aChunk + aoff);
                    ldsm4(A1, aChunk + 2048u + aoff);
                    const u32 boff = (((2u * ks + bSegBit) ^ (u32)lx7) << 4);
                    ldsm4(B0, bBase + boff);
                    ldsm4(B1, bBase + 2048u + boff);
                    ldsm4(B2, bBase + 4096u + boff);
                    ldsm4(B3, bBase + 6144u + boff);
                    mmai16832(accC[0][0], A0, B0[0], B0[1]);
                    mmai16832(accC[0][1], A0, B0[2], B0[3]);
                    mmai16832(accC[0][2], A0, B1[0], B1[1]);
                    mmai16832(accC[0][3], A0, B1[2], B1[3]);
                    mmai16832(accC[0][4], A0, B2[0], B2[1]);
                    mmai16832(accC[0][5], A0, B2[2], B2[3]);
                    mmai16832(accC[0][6], A0, B3[0], B3[1]);
                    mmai16832(accC[0][7], A0, B3[2], B3[3]);
                    mmai16832(accC[1][0], A1, B0[0], B0[1]);
                    mmai16832(accC[1][1], A1, B0[2], B0[3]);
                    mmai16832(accC[1][2], A1, B1[0], B1[1]);
                    mmai16832(accC[1][3], A1, B1[2], B1[3]);
                    mmai16832(accC[1][4], A1, B2[0], B2[1]);
                    mmai16832(accC[1][5], A1, B2[2], B2[3]);
                    mmai16832(accC[1][6], A1, B3[0], B3[1]);
                    mmai16832(accC[1][7], A1, B3[2], B3[3]);
                }
                if (havePrev && cc == 1) epiSlice(accP, 0);
                if (havePrev && cc == 3) epiSlice(accP, 1);
            }
            if (havePrev) epiReduce();
            pv_m = myM; pv_rb = myRb; pv_jt = myJt; pv_dg = dg; havePrev = true;
            int orb = c_rb, om = c_m;
            c_jt++;
            if (c_jt == 64) { c_rb++; c_jt = c_rb; if (c_rb == 64) { c_m++; c_rb = 0; c_jt = 0; } }
            if (c_rb != orb || c_m != om) ab ^= 1;
        };

#pragma unroll 1
        for (int ti = 0; ti < nT; ti++) {
            if (ti & 1) processTile(acc1, acc0, ti);
            else        processTile(acc0, acc1, ti);
        }
        if ((nT - 1) & 1) { epiSlice(acc1, 0); epiSlice(acc1, 1); }
        else              { epiSlice(acc0, 0); epiSlice(acc0, 1); }
        epiReduce();
    }
    grid_bar(2 * NCTA);  // all g_part slots visible

    // ================= Phase 2: per-row LSE + final reduction ==============
    if (bx >= 128) return;
    {
        const int m = bx >> 6, blk = bx & 63;
        const int row = blk * 128 + tid;        // tid < 128? block has 256
        if (tid < 128) {
            const float* gp = g_part + (size_t)m * 64 * NROWS;
            float S = 0.f;
#pragma unroll 8
            for (int s = 0; s < 64; s++) S += gp[((size_t)s << 13) + row];
            float lv = lg2f(S) * LN2_F;
#pragma unroll
            for (int o = 16; o; o >>= 1) lv += __shfl_xor_sync(0xffffffffu, lv, o);
            if ((tid & 31) == 0) rowred[tid >> 5] = lv;
        }
        __syncthreads();
        if (tid == 0)
            g_log_partial[bx] = (rowred[0] + rowred[1]) + (rowred[2] + rowred[3]);

        // last-block final reduction
        __threadfence();
        __shared__ unsigned int isLast;
        if (tid == 0)
            isLast = (atomicAdd(&g_done, 1u) == 127u);
        __syncthreads();
        if (!isLast) return;
        __threadfence();

        if (tid < 128) {
            const int t = tid;
            float s = g_log_partial[t];
            float p = (t < NCTA) ? g_pos_partial[t] : 0.f;
            if (t + 128 < NCTA) p += g_pos_partial[t + 128];
#pragma unroll
            for (int o = 16; o; o >>= 1) {
                s += __shfl_xor_sync(0xffffffffu, s, o);
                p += __shfl_xor_sync(0xffffffffu, p, o);
            }
            if ((t & 31) == 0) { rowred[8 + (t >> 5)] = s; rowred[12 + (t >> 5)] = p; }
        }
        __syncthreads();
        if (tid == 0) {
            float st = (rowred[8] + rowred[9]) + (rowred[10] + rowred[11]);
            float pt = (rowred[12] + rowred[13]) + (rowred[14] + rowred[15]);
            // loss = (sum LSE - (2/T)*sum pos) / (2B),  2/T = 4, 2B = 8192
            out[0] = (st - 4.0f * pt) / 8192.0f;
            g_bar = 0;                           // reset for next graph replay
            g_done = 0;
        }
    }
}

extern "C" void kernel_launch(void* const* d_in, const int* in_sizes, int n_in,
                              void* d_out, int out_size) {
    const float* x1 = (const float*)d_in[0];
    const float* x2 = (const float*)d_in[1];
    const float* z1 = (const float*)d_in[2];
    const float* z2 = (const float*)d_in[3];
    float* out = (float*)d_out;

    cudaFuncSetAttribute(k_fused, cudaFuncAttributeMaxDynamicSharedMemorySize,
                         SMEM_BYTES);

    k_fused<<<NCTA, 256, SMEM_BYTES>>>(x1, x2, z1, z2, out);
}

// round 12
// speedup vs baseline: 1.0316x; 1.0316x over previous
#include <cuda_runtime.h>
#include <cuda_bf16.h>

using u32 = unsigned int;
using u64 = unsigned long long;

#define BPAIR 4096
#define NROWS 8192
#define DDIM  512
// exp(x/T) = 2^(x * 2*log2(e)),  T = 0.5
#define EXP_SCALE 2.8853900817779268f
#define LN2_F     0.6931471805599453f

// ---------------- device scratch (no allocations allowed) ----------------
__device__ unsigned char g_nA[NROWS * DDIM];   // normalized [x1; z2], int8
__device__ unsigned char g_nB[NROWS * DDIM];   // normalized [x2; z1], int8
__device__ float g_scale[2 * NROWS];           // per-row dequant scale
__device__ float g_part[2 * 64 * NROWS];       // [mtx][slot 0..63][row] partials
__device__ float g_log_partial[128];
__device__ float g_pos_partial[1024];
__device__ unsigned int g_done;                // last-block counter (self-reset)

// ---------------- PTX helpers ----------------
__device__ __forceinline__ u32 smem_u32(const void* p) {
    u32 a;
    asm("{ .reg .u64 t; cvta.to.shared.u64 t, %1; cvt.u32.u64 %0, t; }"
        : "=r"(a) : "l"(p));
    return a;
}
__device__ __forceinline__ float ex2f(float x) {
    float y; asm("ex2.approx.f32 %0, %1;" : "=f"(y) : "f"(x)); return y;
}
__device__ __forceinline__ float lg2f(float x) {
    float y; asm("lg2.approx.f32 %0, %1;" : "=f"(y) : "f"(x)); return y;
}
__device__ __forceinline__ void cp_async16(u32 dst, const void* src) {
    asm volatile("cp.async.cg.shared.global [%0], [%1], 16;"
                 :: "r"(dst), "l"(src) : "memory");
}
#define CP_COMMIT() asm volatile("cp.async.commit_group;" ::: "memory")
#define CP_WAIT0()  asm volatile("cp.async.wait_group 0;" ::: "memory")
#define CP_WAIT1()  asm volatile("cp.async.wait_group 1;" ::: "memory")
#define CP_WAIT2()  asm volatile("cp.async.wait_group 2;" ::: "memory")

__device__ __forceinline__ void ldsm4(u32 (&r)[4], u32 addr) {
    asm volatile("ldmatrix.sync.aligned.m8n8.x4.shared.b16 {%0,%1,%2,%3}, [%4];"
        : "=r"(r[0]), "=r"(r[1]), "=r"(r[2]), "=r"(r[3]) : "r"(addr));
}
// INT8 MMA, K=32, s32 accumulate.
__device__ __forceinline__ void mmai16832(int (&d)[4], const u32 (&a)[4],
                                          u32 b0, u32 b1) {
    asm volatile(
        "mma.sync.aligned.m16n8k32.row.col.s32.s8.s8.s32 "
        "{%0,%1,%2,%3}, {%4,%5,%6,%7}, {%8,%9}, {%0,%1,%2,%3};"
        : "+r"(d[0]), "+r"(d[1]), "+r"(d[2]), "+r"(d[3])
        : "r"(a[0]), "r"(a[1]), "r"(a[2]), "r"(a[3]), "r"(b0), "r"(b1));
}

__device__ __forceinline__ u32 pack_s8x4(float a, float b, float c, float d) {
    int ia = __float2int_rn(a), ib = __float2int_rn(b);
    int ic = __float2int_rn(c), id = __float2int_rn(d);
    return (u32)(ia & 0xFF) | ((u32)(ib & 0xFF) << 8) |
           ((u32)(ic & 0xFF) << 16) | ((u32)id << 24);
}

// -------- kernel 1: fused normalize->int8 + pair dots (reads inputs once) --
__global__ void __launch_bounds__(256) k_norm_pos(
    const float* __restrict__ x1, const float* __restrict__ x2,
    const float* __restrict__ z1, const float* __restrict__ z2) {
    int wg   = blockIdx.x * 8 + (threadIdx.x >> 5);   // pair id 0..8191
    int lane = threadIdx.x & 31;
    int h = wg >> 12;
    int i = wg & (BPAIR - 1);
    const float* a = (h ? x2 : x1) + (size_t)i * DDIM;
    const float* b = (h ? z1 : z2) + (size_t)i * DDIM;
    unsigned char* matd = h ? g_nB : g_nA;

    float4 va[4], vb[4];
    float sd = 0.f, sa = 0.f, sb = 0.f, ma = 0.f, mb = 0.f;
#pragma unroll
    for (int k = 0; k < 4; k++) {
        va[k] = ((const float4*)a)[lane + 32 * k];
        vb[k] = ((const float4*)b)[lane + 32 * k];
        sd += va[k].x * vb[k].x + va[k].y * vb[k].y + va[k].z * vb[k].z + va[k].w * vb[k].w;
        sa += va[k].x * va[k].x + va[k].y * va[k].y + va[k].z * va[k].z + va[k].w * va[k].w;
        sb += vb[k].x * vb[k].x + vb[k].y * vb[k].y + vb[k].z * vb[k].z + vb[k].w * vb[k].w;
        ma = fmaxf(ma, fmaxf(fmaxf(fabsf(va[k].x), fabsf(va[k].y)),
                             fmaxf(fabsf(va[k].z), fabsf(va[k].w))));
        mb = fmaxf(mb, fmaxf(fmaxf(fabsf(vb[k].x), fabsf(vb[k].y)),
                             fmaxf(fabsf(vb[k].z), fabsf(vb[k].w))));
    }
#pragma unroll
    for (int o = 16; o; o >>= 1) {
        sd += __shfl_xor_sync(0xffffffffu, sd, o);
        sa += __shfl_xor_sync(0xffffffffu, sa, o);
        sb += __shfl_xor_sync(0xffffffffu, sb, o);
        ma = fmaxf(ma, __shfl_xor_sync(0xffffffffu, ma, o));
        mb = fmaxf(mb, __shfl_xor_sync(0xffffffffu, mb, o));
    }
    float ra = rsqrtf(sa), rb_ = rsqrtf(sb);
    float qa = 127.f / ma, qb = 127.f / mb;
    u32* da = (u32*)(matd + (size_t)i * DDIM);
    u32* db = (u32*)(matd + (size_t)(BPAIR + i) * DDIM);
#pragma unroll
    for (int k = 0; k < 4; k++) {
        da[lane + 32 * k] = pack_s8x4(va[k].x * qa, va[k].y * qa,
                                      va[k].z * qa, va[k].w * qa);
        db[lane + 32 * k] = pack_s8x4(vb[k].x * qb, vb[k].y * qb,
                                      vb[k].z * qb, vb[k].w * qb);
    }
    if (lane == 0) {
        g_scale[h * NROWS + i]         = ma * ra * (1.f / 127.f);
        g_scale[h * NROWS + BPAIR + i] = mb * rb_ * (1.f / 127.f);
    }
    __shared__ float sh[8];
    if (lane == 0) sh[threadIdx.x >> 5] = sd * ra * rb_;
    __syncthreads();
    if (threadIdx.x == 0) {
        float s = 0.f;
        for (int j = 0; j < 8; j++) s += sh[j];
        g_pos_partial[blockIdx.x] = s;
    }
}

// ---------------- kernel 2: symmetric sim GEMM (int8, upper triangle) ------
// 148 CTAs, balanced contiguous partition of all 4160 triangle tiles.
// A row-blocks double-buffered; next strip's A rides in B commit groups.
// B via 4-slot 16KB ring, per-chunk commits, CP_WAIT2 depth.
// NEW: fragment double-buffering — k-step ks+1's 6 ldsm issue while ks's
// 16 MMAs execute, hiding the LDSM->MMA scoreboard latency (tensor pipe
// was only 36% active). Single accumulator, synchronous per-tile epilogue.
#define SMEM_BYTES 200704

__global__ void __launch_bounds__(256, 1) k_simsum() {
    extern __shared__ char smem[];
    const int tid  = threadIdx.x;
    const int wid  = tid >> 5;
    const int lane = tid & 31;
    const int bx   = blockIdx.x;

    // tile range for this CTA: 16 CTAs get 29, 132 get 28
    const int t0 = bx * 28 + (bx < 16 ? bx : 16);
    const int nT = 28 + (bx < 16 ? 1 : 0);
    const int totalChunks = nT * 4;

    // decode compute cursor
    int c_m = t0 / 2080;
    int rrem = t0 % 2080;
    int c_rb = 0;
    while (rrem >= 64 - c_rb) { rrem -= 64 - c_rb; c_rb++; }
    int c_jt = c_rb + rrem;

    // prefetch cursor (B chunks; carries A prefetch on strip change)
    int p_m = c_m, p_rb = c_rb, p_jt = c_jt, p_cc = 0, p_q = 0, p_ab = 0;
    bool p_attach = false;
    int ab = 0;

    const u32 sb     = smem_u32(smem);
    float* rowred    = (float*)smem;            // 256 floats
    float* colred    = rowred + 256;            // 512 floats
    const u32 A_base = sb + 4096u;              // 2 bufs x 4 chunks x 16KB
    const u32 B_base = A_base + 131072u;        // 4 slots x 16KB

    const int warpM = wid >> 1, warpN = wid & 1;
    const int lx7 = lane & 7, l15 = lane & 15;
    const u32 aHi = (u32)(lane >> 4);
    const u32 bSegBit = (u32)((lane >> 3) & 1);
    const u32 aRowOff = (u32)(warpM * 32 + l15) * 128u;
    const u32 bRowOff = (u32)(warpN * 64 + lx7 + ((lane >> 4) << 3)) * 128u;
    const int qr = lane >> 2, qc = lane & 3;
    const int rowLo0 = warpM * 32 + qr;
    const int colB0  = warpN * 64 + qc * 2;

    // ---- prologue: A block for first strip into buf 0 (group 0) ----
    {
        const unsigned char* mp = c_m ? g_nB : g_nA;
        const unsigned char* abase = mp + (size_t)(c_rb * 128) * DDIM;
#pragma unroll
        for (int t = 0; t < 16; t++) {
            int idx = tid + t * 256;            // 0..4095
            int ch = idx >> 10, rem = idx & 1023, r = rem >> 3, sg = rem & 7;
            cp_async16(A_base + (u32)(ch * 16384 + r * 128 + ((sg ^ (r & 7)) << 4)),
                       abase + (size_t)r * DDIM + ch * 128 + sg * 16);
        }
        CP_COMMIT();
    }

    auto advancePF = [&]() {
        int orb = p_rb, om = p_m;
        p_jt++;
        if (p_jt == 64) { p_rb++; p_jt = p_rb; if (p_rb == 64) { p_m++; p_rb = 0; p_jt = 0; } }
        bool ns = (p_rb != orb) || (p_m != om);
        p_attach = ns;
        if (ns) p_ab ^= 1;
    };
    auto issuePF = [&]() {
        const unsigned char* mp = p_m ? g_nB : g_nA;
        u32 slot = B_base + (u32)(p_q & 3) * 16384u;
        const unsigned char* srcB = mp + (size_t)(p_jt * 128) * DDIM + p_cc * 128;
#pragma unroll
        for (int t = 0; t < 4; t++) {
            int idx = tid + t * 256;
            int r = idx >> 3, sg = idx & 7;
            cp_async16(slot + (u32)(r * 128 + ((sg ^ (r & 7)) << 4)),
                       srcB + (size_t)r * DDIM + sg * 16);
        }
        if (p_attach) {   // A quarter p_cc of the new strip into buf p_ab
            u32 dstA = A_base + (u32)p_ab * 65536u + (u32)p_cc * 16384u;
            const unsigned char* srcA = mp + (size_t)(p_rb * 128) * DDIM + p_cc * 128;
#pragma unroll
            for (int t = 0; t < 4; t++) {
                int idx = tid + t * 256;
                int r = idx >> 3, sg = idx & 7;
                cp_async16(dstA + (u32)(r * 128 + ((sg ^ (r & 7)) << 4)),
                           srcA + (size_t)r * DDIM + sg * 16);
            }
        }
        CP_COMMIT();
        p_q++; p_cc++;
        if (p_cc == 4) { p_cc = 0; advancePF(); }
    };
    issuePF();
    issuePF();

    int acc[2][8][4];
#pragma unroll
    for (int mi = 0; mi < 2; mi++)
#pragma unroll
        for (int ni = 0; ni < 8; ni++)
#pragma unroll
            for (int e = 0; e < 4; e++) acc[mi][ni][e] = 0;

#pragma unroll 1
    for (int ti = 0; ti < nT; ti++) {
        const bool dg = (c_jt == c_rb);
        const int myM = c_m, myRb = c_rb, myJt = c_jt;

#pragma unroll 1
        for (int cc = 0; cc < 4; cc++) {
            const int q = ti * 4 + cc;
            if (q + 2 < totalChunks) { issuePF(); CP_WAIT2(); }
            else if (q + 1 < totalChunks) { CP_WAIT1(); }
            else { CP_WAIT0(); }
            __syncthreads();

            const u32 aChunk = A_base + (u32)ab * 65536u + (u32)cc * 16384u + aRowOff;
            const u32 bBase  = B_base + (u32)(q & 3) * 16384u + bRowOff;

            // fragment double-buffer: load ks+1 while ks's MMAs issue
            u32 Af[2][2][4], Bf[2][4][4];
#define LDFRAGS(buf, ks) do {                                            \
            const u32 aoff_ = (((2u * (ks) + aHi) ^ (u32)lx7) << 4);     \
            ldsm4(Af[buf][0], aChunk + aoff_);                           \
            ldsm4(Af[buf][1], aChunk + 2048u + aoff_);                   \
            const u32 boff_ = (((2u * (ks) + bSegBit) ^ (u32)lx7) << 4); \
            ldsm4(Bf[buf][0], bBase + boff_);                            \
            ldsm4(Bf[buf][1], bBase + 2048u + boff_);                    \
            ldsm4(Bf[buf][2], bBase + 4096u + boff_);                    \
            ldsm4(Bf[buf][3], bBase + 6144u + boff_);                    \
        } while (0)

            LDFRAGS(0, 0);
#pragma unroll
            for (int ks = 0; ks < 4; ks++) {
                const int cur = ks & 1, nxt = cur ^ 1;
                if (ks < 3) LDFRAGS(nxt, ks + 1);
                mmai16832(acc[0][0], Af[cur][0], Bf[cur][0][0], Bf[cur][0][1]);
                mmai16832(acc[0][1], Af[cur][0], Bf[cur][0][2], Bf[cur][0][3]);
                mmai16832(acc[0][2], Af[cur][0], Bf[cur][1][0], Bf[cur][1][1]);
                mmai16832(acc[0][3], Af[cur][0], Bf[cur][1][2], Bf[cur][1][3]);
                mmai16832(acc[0][4], Af[cur][0], Bf[cur][2][0], Bf[cur][2][1]);
                mmai16832(acc[0][5], Af[cur][0], Bf[cur][2][2], Bf[cur][2][3]);
                mmai16832(acc[0][6], Af[cur][0], Bf[cur][3][0], Bf[cur][3][1]);
                mmai16832(acc[0][7], Af[cur][0], Bf[cur][3][2], Bf[cur][3][3]);
                mmai16832(acc[1][0], Af[cur][1], Bf[cur][0][0], Bf[cur][0][1]);
                mmai16832(acc[1][1], Af[cur][1], Bf[cur][0][2], Bf[cur][0][3]);
                mmai16832(acc[1][2], Af[cur][1], Bf[cur][1][0], Bf[cur][1][1]);
                mmai16832(acc[1][3], Af[cur][1], Bf[cur][1][2], Bf[cur][1][3]);
                mmai16832(acc[1][4], Af[cur][1], Bf[cur][2][0], Bf[cur][2][1]);
                mmai16832(acc[1][5], Af[cur][1], Bf[cur][2][2], Bf[cur][2][3]);
                mmai16832(acc[1][6], Af[cur][1], Bf[cur][3][0], Bf[cur][3][1]);
                mmai16832(acc[1][7], Af[cur][1], Bf[cur][3][2], Bf[cur][3][3]);
            }
#undef LDFRAGS
        }

        // ---- synchronous epilogue: dequant + exp + row/col sums ----
        {
            const float* gsc = g_scale + (size_t)myM * NROWS;
            float rsum[2][2] = {{0.f, 0.f}, {0.f, 0.f}};
            float csum[8][2];
#pragma unroll
            for (int ni = 0; ni < 8; ni++) { csum[ni][0] = 0.f; csum[ni][1] = 0.f; }
#pragma unroll
            for (int mi = 0; mi < 2; mi++) {
                float f0 = __ldg(gsc + myRb * 128 + rowLo0 + mi * 16) * EXP_SCALE;
                float f1 = __ldg(gsc + myRb * 128 + rowLo0 + mi * 16 + 8) * EXP_SCALE;
                const int rlo = rowLo0 + mi * 16, rhi = rlo + 8;
#pragma unroll
                for (int ni = 0; ni < 8; ni++) {
                    float s0 = __ldg(gsc + myJt * 128 + colB0 + ni * 8);
                    float s1 = __ldg(gsc + myJt * 128 + colB0 + ni * 8 + 1);
                    const int colb = colB0 + ni * 8;
                    float e0 = ex2f(__int2float_rn(acc[mi][ni][0]) * (f0 * s0));
                    float e1 = ex2f(__int2float_rn(acc[mi][ni][1]) * (f0 * s1));
                    float e2 = ex2f(__int2float_rn(acc[mi][ni][2]) * (f1 * s0));
                    float e3 = ex2f(__int2float_rn(acc[mi][ni][3]) * (f1 * s1));
                    if (dg) {
                        if (colb     == rlo) e0 = 0.f;
                        if (colb + 1 == rlo) e1 = 0.f;
                        if (colb     == rhi) e2 = 0.f;
                        if (colb + 1 == rhi) e3 = 0.f;
                    }
                    rsum[mi][0] += e0 + e1;
                    rsum[mi][1] += e2 + e3;
                    csum[ni][0] += e0 + e2;
                    csum[ni][1] += e1 + e3;
                    acc[mi][ni][0] = 0; acc[mi][ni][1] = 0;
                    acc[mi][ni][2] = 0; acc[mi][ni][3] = 0;
                }
            }
            // row reduce across quad columns (qc)
#pragma unroll
            for (int mi = 0; mi < 2; mi++)
#pragma unroll
                for (int h = 0; h < 2; h++) {
                    float v = rsum[mi][h];
                    v += __shfl_xor_sync(0xffffffffu, v, 1);
                    v += __shfl_xor_sync(0xffffffffu, v, 2);
                    if (qc == 0)
                        rowred[warpN * 128 + rowLo0 + mi * 16 + 8 * h] = v;
                }
            // col reduce across quad rows (qr)
#pragma unroll
            for (int ni = 0; ni < 8; ni++)
#pragma unroll
                for (int j = 0; j < 2; j++) {
                    float v = csum[ni][j];
                    v += __shfl_xor_sync(0xffffffffu, v, 4);
                    v += __shfl_xor_sync(0xffffffffu, v, 8);
                    v += __shfl_xor_sync(0xffffffffu, v, 16);
                    if (lane < 4)
                        colred[warpM * 128 + warpN * 64 + qc * 2 + ni * 8 + j] = v;
                }
            __syncthreads();
            float* gpart = g_part + (size_t)myM * 64 * NROWS;
            if (tid < 128) {
                float rv = rowred[tid] + rowred[128 + tid];
                gpart[((size_t)myJt << 13) + myRb * 128 + tid] = rv;
                if (!dg) {
                    float cv = colred[tid] + colred[128 + tid] +
                               colred[256 + tid] + colred[384 + tid];
                    gpart[((size_t)myRb << 13) + myJt * 128 + tid] = cv;
                }
            }
            // next tile's first-chunk __syncthreads orders rowred/colred reuse
        }

        // advance compute cursor; flip A buffer on strip change
        int orb = c_rb, om = c_m;
        c_jt++;
        if (c_jt == 64) { c_rb++; c_jt = c_rb; if (c_rb == 64) { c_m++; c_rb = 0; c_jt = 0; } }
        if (c_rb != orb || c_m != om) ab ^= 1;
    }
}

// -------- kernel 3: per-row LSE + fused final reduction (last block) -------
__global__ void __launch_bounds__(128) k_lse_final(float* __restrict__ out) {
    const int bid = blockIdx.x;        // 0..127: mtx = bid>>6, blk = bid&63
    const int m = bid >> 6, blk = bid & 63;
    const int row = blk * 128 + threadIdx.x;
    const float* gp = g_part + (size_t)m * 64 * NROWS;
    float S = 0.f;
#pragma unroll 8
    for (int s = 0; s < 64; s++) S += gp[((size_t)s << 13) + row];
    float lv = lg2f(S) * LN2_F;
    __shared__ float sh[4];
#pragma unroll
    for (int o = 16; o; o >>= 1) lv += __shfl_xor_sync(0xffffffffu, lv, o);
    if ((threadIdx.x & 31) == 0) sh[threadIdx.x >> 5] = lv;
    __syncthreads();
    if (threadIdx.x == 0)
        g_log_partial[bid] = (sh[0] + sh[1]) + (sh[2] + sh[3]);

    // last-block final reduction
    __threadfence();
    __shared__ unsigned int isLast;
    if (threadIdx.x == 0)
        isLast = (atomicAdd(&g_done, 1u) == 127u);
    __syncthreads();
    if (!isLast) return;
    __threadfence();

    const int t = threadIdx.x;
    float s = g_log_partial[t];                 // 128 elements, 1 per thread
    float p = 0.f;
#pragma unroll
    for (int i = 0; i < 8; i++) p += g_pos_partial[t + 128 * i];   // 1024 total
#pragma unroll
    for (int o = 16; o; o >>= 1) {
        s += __shfl_xor_sync(0xffffffffu, s, o);
        p += __shfl_xor_sync(0xffffffffu, p, o);
    }
    __shared__ float shs[4], shp[4];
    if ((t & 31) == 0) { shs[t >> 5] = s; shp[t >> 5] = p; }
    __syncthreads();
    if (t == 0) {
        float st = (shs[0] + shs[1]) + (shs[2] + shs[3]);
        float pt = (shp[0] + shp[1]) + (shp[2] + shp[3]);
        // loss = (sum LSE - (2/T)*sum pos) / (2B),  2/T = 4, 2B = 8192
        out[0] = (st - 4.0f * pt) / 8192.0f;
        g_done = 0;                              // reset for next graph replay
    }
}

extern "C" void kernel_launch(void* const* d_in, const int* in_sizes, int n_in,
                              void* d_out, int out_size) {
    const float* x1 = (const float*)d_in[0];
    const float* x2 = (const float*)d_in[1];
    const float* z1 = (const float*)d_in[2];
    const float* z2 = (const float*)d_in[3];
    float* out = (float*)d_out;

    cudaFuncSetAttribute(k_simsum, cudaFuncAttributeMaxDynamicSharedMemorySize,
                         SMEM_BYTES);

    k_norm_pos<<<1024, 256>>>(x1, x2, z1, z2);
    k_simsum<<<148, 256, SMEM_BYTES>>>();
    k_lse_final<<<128, 128>>>(out);
}

// round 13
// speedup vs baseline: 1.0606x; 1.0281x over previous
#include <cuda_runtime.h>
#include <cuda_bf16.h>

using u32 = unsigned int;
using u64 = unsigned long long;

#define BPAIR 4096
#define NROWS 8192
#define DDIM  512
// exp(x/T) = 2^(x * 2*log2(e)),  T = 0.5
#define EXP_SCALE 2.8853900817779268f
#define LN2_F     0.6931471805599453f

// ---------------- device scratch (no allocations allowed) ----------------
__device__ unsigned char g_nA[NROWS * DDIM];   // normalized [x1; z2], int8
__device__ unsigned char g_nB[NROWS * DDIM];   // normalized [x2; z1], int8
__device__ float g_scale[2 * NROWS];           // per-row dequant scale
__device__ float g_part[2 * 64 * NROWS];       // [mtx][slot 0..63][row] partials
__device__ float g_log_partial[128];
__device__ float g_pos_partial[1024];
__device__ unsigned int g_done;                // last-block counter (self-reset)

// ---------------- PTX helpers ----------------
__device__ __forceinline__ u32 smem_u32(const void* p) {
    u32 a;
    asm("{ .reg .u64 t; cvta.to.shared.u64 t, %1; cvt.u32.u64 %0, t; }"
        : "=r"(a) : "l"(p));
    return a;
}
__device__ __forceinline__ float ex2f(float x) {
    float y; asm("ex2.approx.f32 %0, %1;" : "=f"(y) : "f"(x)); return y;
}
__device__ __forceinline__ float lg2f(float x) {
    float y; asm("lg2.approx.f32 %0, %1;" : "=f"(y) : "f"(x)); return y;
}
__device__ __forceinline__ void cp_async16(u32 dst, const void* src) {
    asm volatile("cp.async.cg.shared.global [%0], [%1], 16;"
                 :: "r"(dst), "l"(src) : "memory");
}
#define CP_COMMIT() asm volatile("cp.async.commit_group;" ::: "memory")
#define CP_WAIT0()  asm volatile("cp.async.wait_group 0;" ::: "memory")
#define CP_WAIT1()  asm volatile("cp.async.wait_group 1;" ::: "memory")
#define CP_WAIT2()  asm volatile("cp.async.wait_group 2;" ::: "memory")

__device__ __forceinline__ void ldsm4(u32 (&r)[4], u32 addr) {
    asm volatile("ldmatrix.sync.aligned.m8n8.x4.shared.b16 {%0,%1,%2,%3}, [%4];"
        : "=r"(r[0]), "=r"(r[1]), "=r"(r[2]), "=r"(r[3]) : "r"(addr));
}
// INT8 MMA, K=32, s32 accumulate.
__device__ __forceinline__ void mmai16832(int (&d)[4], const u32 (&a)[4],
                                          u32 b0, u32 b1) {
    asm volatile(
        "mma.sync.aligned.m16n8k32.row.col.s32.s8.s8.s32 "
        "{%0,%1,%2,%3}, {%4,%5,%6,%7}, {%8,%9}, {%0,%1,%2,%3};"
        : "+r"(d[0]), "+r"(d[1]), "+r"(d[2]), "+r"(d[3])
        : "r"(a[0]), "r"(a[1]), "r"(a[2]), "r"(a[3]), "r"(b0), "r"(b1));
}

__device__ __forceinline__ u32 pack_s8x4(float a, float b, float c, float d) {
    int ia = __float2int_rn(a), ib = __float2int_rn(b);
    int ic = __float2int_rn(c), id = __float2int_rn(d);
    return (u32)(ia & 0xFF) | ((u32)(ib & 0xFF) << 8) |
           ((u32)(ic & 0xFF) << 16) | ((u32)id << 24);
}

// -------- kernel 1: fused normalize->int8 + pair dots (reads inputs once) --
__global__ void __launch_bounds__(256) k_norm_pos(
    const float* __restrict__ x1, const float* __restrict__ x2,
    const float* __restrict__ z1, const float* __restrict__ z2) {
    int wg   = blockIdx.x * 8 + (threadIdx.x >> 5);   // pair id 0..8191
    int lane = threadIdx.x & 31;
    int h = wg >> 12;
    int i = wg & (BPAIR - 1);
    const float* a = (h ? x2 : x1) + (size_t)i * DDIM;
    const float* b = (h ? z1 : z2) + (size_t)i * DDIM;
    unsigned char* matd = h ? g_nB : g_nA;

    float4 va[4], vb[4];
    float sd = 0.f, sa = 0.f, sb = 0.f, ma = 0.f, mb = 0.f;
#pragma unroll
    for (int k = 0; k < 4; k++) {
        va[k] = ((const float4*)a)[lane + 32 * k];
        vb[k] = ((const float4*)b)[lane + 32 * k];
        sd += va[k].x * vb[k].x + va[k].y * vb[k].y + va[k].z * vb[k].z + va[k].w * vb[k].w;
        sa += va[k].x * va[k].x + va[k].y * va[k].y + va[k].z * va[k].z + va[k].w * va[k].w;
        sb += vb[k].x * vb[k].x + vb[k].y * vb[k].y + vb[k].z * vb[k].z + vb[k].w * vb[k].w;
        ma = fmaxf(ma, fmaxf(fmaxf(fabsf(va[k].x), fabsf(va[k].y)),
                             fmaxf(fabsf(va[k].z), fabsf(va[k].w))));
        mb = fmaxf(mb, fmaxf(fmaxf(fabsf(vb[k].x), fabsf(vb[k].y)),
                             fmaxf(fabsf(vb[k].z), fabsf(vb[k].w))));
    }
#pragma unroll
    for (int o = 16; o; o >>= 1) {
        sd += __shfl_xor_sync(0xffffffffu, sd, o);
        sa += __shfl_xor_sync(0xffffffffu, sa, o);
        sb += __shfl_xor_sync(0xffffffffu, sb, o);
        ma = fmaxf(ma, __shfl_xor_sync(0xffffffffu, ma, o));
        mb = fmaxf(mb, __shfl_xor_sync(0xffffffffu, mb, o));
    }
    float ra = rsqrtf(sa), rb_ = rsqrtf(sb);
    float qa = 127.f / ma, qb = 127.f / mb;
    u32* da = (u32*)(matd + (size_t)i * DDIM);
    u32* db = (u32*)(matd + (size_t)(BPAIR + i) * DDIM);
#pragma unroll
    for (int k = 0; k < 4; k++) {
        da[lane + 32 * k] = pack_s8x4(va[k].x * qa, va[k].y * qa,
                                      va[k].z * qa, va[k].w * qa);
        db[lane + 32 * k] = pack_s8x4(vb[k].x * qb, vb[k].y * qb,
                                      vb[k].z * qb, vb[k].w * qb);
    }
    if (lane == 0) {
        g_scale[h * NROWS + i]         = ma * ra * (1.f / 127.f);
        g_scale[h * NROWS + BPAIR + i] = mb * rb_ * (1.f / 127.f);
    }
    __shared__ float sh[8];
    if (lane == 0) sh[threadIdx.x >> 5] = sd * ra * rb_;
    __syncthreads();
    if (threadIdx.x == 0) {
        float s = 0.f;
        for (int j = 0; j < 8; j++) s += sh[j];
        g_pos_partial[blockIdx.x] = s;
    }
    // PDL: allow the dependent GEMM grid to be staged
    cudaTriggerProgrammaticLaunchCompletion();
}

// ---------------- kernel 2: symmetric sim GEMM (int8, upper triangle) ------
// 148 CTAs, balanced contiguous partition of all 4160 triangle tiles.
// A row-blocks double-buffered; next strip's A rides in B commit groups.
// B via 4-slot 16KB ring, per-chunk commits, CP_WAIT2 depth.
// Fragment double-buffering in the k-step loop; synchronous per-tile epilogue.
// PDL: grid is pre-staged during k_norm_pos; sync before first data touch.
#define SMEM_BYTES 200704

__global__ void __launch_bounds__(256, 1) k_simsum() {
    extern __shared__ char smem[];
    const int tid  = threadIdx.x;
    const int wid  = tid >> 5;
    const int lane = tid & 31;
    const int bx   = blockIdx.x;

    // tile range for this CTA: 16 CTAs get 29, 132 get 28
    const int t0 = bx * 28 + (bx < 16 ? bx : 16);
    const int nT = 28 + (bx < 16 ? 1 : 0);
    const int totalChunks = nT * 4;

    // decode compute cursor
    int c_m = t0 / 2080;
    int rrem = t0 % 2080;
    int c_rb = 0;
    while (rrem >= 64 - c_rb) { rrem -= 64 - c_rb; c_rb++; }
    int c_jt = c_rb + rrem;

    // prefetch cursor (B chunks; carries A prefetch on strip change)
    int p_m = c_m, p_rb = c_rb, p_jt = c_jt, p_cc = 0, p_q = 0, p_ab = 0;
    bool p_attach = false;
    int ab = 0;

    const u32 sb     = smem_u32(smem);
    float* rowred    = (float*)smem;            // 256 floats
    float* colred    = rowred + 256;            // 512 floats
    const u32 A_base = sb + 4096u;              // 2 bufs x 4 chunks x 16KB
    const u32 B_base = A_base + 131072u;        // 4 slots x 16KB

    const int warpM = wid >> 1, warpN = wid & 1;
    const int lx7 = lane & 7, l15 = lane & 15;
    const u32 aHi = (u32)(lane >> 4);
    const u32 bSegBit = (u32)((lane >> 3) & 1);
    const u32 aRowOff = (u32)(warpM * 32 + l15) * 128u;
    const u32 bRowOff = (u32)(warpN * 64 + lx7 + ((lane >> 4) << 3)) * 128u;
    const int qr = lane >> 2, qc = lane & 3;
    const int rowLo0 = warpM * 32 + qr;
    const int colB0  = warpN * 64 + qc * 2;

    // PDL: wait for k_norm_pos's writes (g_nA/g_nB/g_scale) to be visible
    cudaGridDependencySynchronize();

    // ---- prologue: A block for first strip into buf 0 (group 0) ----
    {
        const unsigned char* mp = c_m ? g_nB : g_nA;
        const unsigned char* abase = mp + (size_t)(c_rb * 128) * DDIM;
#pragma unroll
        for (int t = 0; t < 16; t++) {
            int idx = tid + t * 256;            // 0..4095
            int ch = idx >> 10, rem = idx & 1023, r = rem >> 3, sg = rem & 7;
            cp_async16(A_base + (u32)(ch * 16384 + r * 128 + ((sg ^ (r & 7)) << 4)),
                       abase + (size_t)r * DDIM + ch * 128 + sg * 16);
        }
        CP_COMMIT();
    }

    auto advancePF = [&]() {
        int orb = p_rb, om = p_m;
        p_jt++;
        if (p_jt == 64) { p_rb++; p_jt = p_rb; if (p_rb == 64) { p_m++; p_rb = 0; p_jt = 0; } }
        bool ns = (p_rb != orb) || (p_m != om);
        p_attach = ns;
        if (ns) p_ab ^= 1;
    };
    auto issuePF = [&]() {
        const unsigned char* mp = p_m ? g_nB : g_nA;
        u32 slot = B_base + (u32)(p_q & 3) * 16384u;
        const unsigned char* srcB = mp + (size_t)(p_jt * 128) * DDIM + p_cc * 128;
#pragma unroll
        for (int t = 0; t < 4; t++) {
            int idx = tid + t * 256;
            int r = idx >> 3, sg = idx & 7;
            cp_async16(slot + (u32)(r * 128 + ((sg ^ (r & 7)) << 4)),
                       srcB + (size_t)r * DDIM + sg * 16);
        }
        if (p_attach) {   // A quarter p_cc of the new strip into buf p_ab
            u32 dstA = A_base + (u32)p_ab * 65536u + (u32)p_cc * 16384u;
            const unsigned char* srcA = mp + (size_t)(p_rb * 128) * DDIM + p_cc * 128;
#pragma unroll
            for (int t = 0; t < 4; t++) {
                int idx = tid + t * 256;
                int r = idx >> 3, sg = idx & 7;
                cp_async16(dstA + (u32)(r * 128 + ((sg ^ (r & 7)) << 4)),
                           srcA + (size_t)r * DDIM + sg * 16);
            }
        }
        CP_COMMIT();
        p_q++; p_cc++;
        if (p_cc == 4) { p_cc = 0; advancePF(); }
    };
    issuePF();
    issuePF();

    int acc[2][8][4];
#pragma unroll
    for (int mi = 0; mi < 2; mi++)
#pragma unroll
        for (int ni = 0; ni < 8; ni++)
#pragma unroll
            for (int e = 0; e < 4; e++) acc[mi][ni][e] = 0;

#pragma unroll 1
    for (int ti = 0; ti < nT; ti++) {
        const bool dg = (c_jt == c_rb);
        const int myM = c_m, myRb = c_rb, myJt = c_jt;

#pragma unroll 1
        for (int cc = 0; cc < 4; cc++) {
            const int q = ti * 4 + cc;
            if (q + 2 < totalChunks) { issuePF(); CP_WAIT2(); }
            else if (q + 1 < totalChunks) { CP_WAIT1(); }
            else { CP_WAIT0(); }
            __syncthreads();

            const u32 aChunk = A_base + (u32)ab * 65536u + (u32)cc * 16384u + aRowOff;
            const u32 bBase  = B_base + (u32)(q & 3) * 16384u + bRowOff;

            // fragment double-buffer: load ks+1 while ks's MMAs issue
            u32 Af[2][2][4], Bf[2][4][4];
#define LDFRAGS(buf, ks) do {                                            \
            const u32 aoff_ = (((2u * (ks) + aHi) ^ (u32)lx7) << 4);     \
            ldsm4(Af[buf][0], aChunk + aoff_);                           \
            ldsm4(Af[buf][1], aChunk + 2048u + aoff_);                   \
            const u32 boff_ = (((2u * (ks) + bSegBit) ^ (u32)lx7) << 4); \
            ldsm4(Bf[buf][0], bBase + boff_);                            \
            ldsm4(Bf[buf][1], bBase + 2048u + boff_);                    \
            ldsm4(Bf[buf][2], bBase + 4096u + boff_);                    \
            ldsm4(Bf[buf][3], bBase + 6144u + boff_);                    \
        } while (0)

            LDFRAGS(0, 0);
#pragma unroll
            for (int ks = 0; ks < 4; ks++) {
                const int cur = ks & 1, nxt = cur ^ 1;
                if (ks < 3) LDFRAGS(nxt, ks + 1);
                mmai16832(acc[0][0], Af[cur][0], Bf[cur][0][0], Bf[cur][0][1]);
                mmai16832(acc[0][1], Af[cur][0], Bf[cur][0][2], Bf[cur][0][3]);
                mmai16832(acc[0][2], Af[cur][0], Bf[cur][1][0], Bf[cur][1][1]);
                mmai16832(acc[0][3], Af[cur][0], Bf[cur][1][2], Bf[cur][1][3]);
                mmai16832(acc[0][4], Af[cur][0], Bf[cur][2][0], Bf[cur][2][1]);
                mmai16832(acc[0][5], Af[cur][0], Bf[cur][2][2], Bf[cur][2][3]);
                mmai16832(acc[0][6], Af[cur][0], Bf[cur][3][0], Bf[cur][3][1]);
                mmai16832(acc[0][7], Af[cur][0], Bf[cur][3][2], Bf[cur][3][3]);
                mmai16832(acc[1][0], Af[cur][1], Bf[cur][0][0], Bf[cur][0][1]);
                mmai16832(acc[1][1], Af[cur][1], Bf[cur][0][2], Bf[cur][0][3]);
                mmai16832(acc[1][2], Af[cur][1], Bf[cur][1][0], Bf[cur][1][1]);
                mmai16832(acc[1][3], Af[cur][1], Bf[cur][1][2], Bf[cur][1][3]);
                mmai16832(acc[1][4], Af[cur][1], Bf[cur][2][0], Bf[cur][2][1]);
                mmai16832(acc[1][5], Af[cur][1], Bf[cur][2][2], Bf[cur][2][3]);
                mmai16832(acc[1][6], Af[cur][1], Bf[cur][3][0], Bf[cur][3][1]);
                mmai16832(acc[1][7], Af[cur][1], Bf[cur][3][2], Bf[cur][3][3]);
            }
#undef LDFRAGS
        }

        // ---- synchronous epilogue: dequant + exp + row/col sums ----
        {
            const float* gsc = g_scale + (size_t)myM * NROWS;
            float rsum[2][2] = {{0.f, 0.f}, {0.f, 0.f}};
            float csum[8][2];
#pragma unroll
            for (int ni = 0; ni < 8; ni++) { csum[ni][0] = 0.f; csum[ni][1] = 0.f; }
#pragma unroll
            for (int mi = 0; mi < 2; mi++) {
                float f0 = __ldg(gsc + myRb * 128 + rowLo0 + mi * 16) * EXP_SCALE;
                float f1 = __ldg(gsc + myRb * 128 + rowLo0 + mi * 16 + 8) * EXP_SCALE;
                const int rlo = rowLo0 + mi * 16, rhi = rlo + 8;
#pragma unroll
                for (int ni = 0; ni < 8; ni++) {
                    float s0 = __ldg(gsc + myJt * 128 + colB0 + ni * 8);
                    float s1 = __ldg(gsc + myJt * 128 + colB0 + ni * 8 + 1);
                    const int colb = colB0 + ni * 8;
                    float e0 = ex2f(__int2float_rn(acc[mi][ni][0]) * (f0 * s0));
                    float e1 = ex2f(__int2float_rn(acc[mi][ni][1]) * (f0 * s1));
                    float e2 = ex2f(__int2float_rn(acc[mi][ni][2]) * (f1 * s0));
                    float e3 = ex2f(__int2float_rn(acc[mi][ni][3]) * (f1 * s1));
                    if (dg) {
                        if (colb     == rlo) e0 = 0.f;
                        if (colb + 1 == rlo) e1 = 0.f;
                        if (colb     == rhi) e2 = 0.f;
                        if (colb + 1 == rhi) e3 = 0.f;
                    }
                    rsum[mi][0] += e0 + e1;
                    rsum[mi][1] += e2 + e3;
                    csum[ni][0] += e0 + e2;
                    csum[ni][1] += e1 + e3;
                    acc[mi][ni][0] = 0; acc[mi][ni][1] = 0;
                    acc[mi][ni][2] = 0; acc[mi][ni][3] = 0;
                }
            }
            // row reduce across quad columns (qc)
#pragma unroll
            for (int mi = 0; mi < 2; mi++)
#pragma unroll
                for (int h = 0; h < 2; h++) {
                    float v = rsum[mi][h];
                    v += __shfl_xor_sync(0xffffffffu, v, 1);
                    v += __shfl_xor_sync(0xffffffffu, v, 2);
                    if (qc == 0)
                        rowred[warpN * 128 + rowLo0 + mi * 16 + 8 * h] = v;
                }
            // col reduce across quad rows (qr)
#pragma unroll
            for (int ni = 0; ni < 8; ni++)
#pragma unroll
                for (int j = 0; j < 2; j++) {
                    float v = csum[ni][j];
                    v += __shfl_xor_sync(0xffffffffu, v, 4);
                    v += __shfl_xor_sync(0xffffffffu, v, 8);
                    v += __shfl_xor_sync(0xffffffffu, v, 16);
                    if (lane < 4)
                        colred[warpM * 128 + warpN * 64 + qc * 2 + ni * 8 + j] = v;
                }
            __syncthreads();
            float* gpart = g_part + (size_t)myM * 64 * NROWS;
            if (tid < 128) {
                float rv = rowred[tid] + rowred[128 + tid];
                gpart[((size_t)myJt << 13) + myRb * 128 + tid] = rv;
                if (!dg) {
                    float cv = colred[tid] + colred[128 + tid] +
                               colred[256 + tid] + colred[384 + tid];
                    gpart[((size_t)myRb << 13) + myJt * 128 + tid] = cv;
                }
            }
            // next tile's first-chunk __syncthreads orders rowred/colred reuse
        }

        // advance compute cursor; flip A buffer on strip change
        int orb = c_rb, om = c_m;
        c_jt++;
        if (c_jt == 64) { c_rb++; c_jt = c_rb; if (c_rb == 64) { c_m++; c_rb = 0; c_jt = 0; } }
        if (c_rb != orb || c_m != om) ab ^= 1;
    }
    cudaTriggerProgrammaticLaunchCompletion();
}

// -------- kernel 3: per-row LSE + fused final reduction (last block) -------
__global__ void __launch_bounds__(128) k_lse_final(float* __restrict__ out) {
    const int bid = blockIdx.x;        // 0..127: mtx = bid>>6, blk = bid&63
    const int m = bid >> 6, blk = bid & 63;
    const int row = blk * 128 + threadIdx.x;

    // PDL: wait for k_simsum's g_part writes
    cudaGridDependencySynchronize();

    const float* gp = g_part + (size_t)m * 64 * NROWS;
    float S = 0.f;
#pragma unroll 8
    for (int s = 0; s < 64; s++) S += gp[((size_t)s << 13) + row];
    float lv = lg2f(S) * LN2_F;
    __shared__ float sh[4];
#pragma unroll
    for (int o = 16; o; o >>= 1) lv += __shfl_xor_sync(0xffffffffu, lv, o);
    if ((threadIdx.x & 31) == 0) sh[threadIdx.x >> 5] = lv;
    __syncthreads();
    if (threadIdx.x == 0)
        g_log_partial[bid] = (sh[0] + sh[1]) + (sh[2] + sh[3]);

    // last-block final reduction
    __threadfence();
    __shared__ unsigned int isLast;
    if (threadIdx.x == 0)
        isLast = (atomicAdd(&g_done, 1u) == 127u);
    __syncthreads();
    if (!isLast) return;
    __threadfence();

    const int t = threadIdx.x;
    float s = g_log_partial[t];                 // 128 elements, 1 per thread
    float p = 0.f;
#pragma unroll
    for (int i = 0; i < 8; i++) p += g_pos_partial[t + 128 * i];   // 1024 total
#pragma unroll
    for (int o = 16; o; o >>= 1) {
        s += __shfl_xor_sync(0xffffffffu, s, o);
        p += __shfl_xor_sync(0xffffffffu, p, o);
    }
    __shared__ float shs[4], shp[4];
    if ((t & 31) == 0) { shs[t >> 5] = s; shp[t >> 5] = p; }
    __syncthreads();
    if (t == 0) {
        float st = (shs[0] + shs[1]) + (shs[2] + shs[3]);
        float pt = (shp[0] + shp[1]) + (shp[2] + shp[3]);
        // loss = (sum LSE - (2/T)*sum pos) / (2B),  2/T = 4, 2B = 8192
        out[0] = (st - 4.0f * pt) / 8192.0f;
        g_done = 0;                              // reset for next graph replay
    }
}

extern "C" void kernel_launch(void* const* d_in, const int* in_sizes, int n_in,
                              void* d_out, int out_size) {
    const float* x1 = (const float*)d_in[0];
    const float* x2 = (const float*)d_in[1];
    const float* z1 = (const float*)d_in[2];
    const float* z2 = (const float*)d_in[3];
    float* out = (float*)d_out;

    cudaFuncSetAttribute(k_simsum, cudaFuncAttributeMaxDynamicSharedMemorySize,
                         SMEM_BYTES);

    k_norm_pos<<<1024, 256>>>(x1, x2, z1, z2);

    // k_simsum with PDL (pre-staged while k_norm_pos drains)
    {
        cudaLaunchConfig_t cfg = {};
        cfg.gridDim = dim3(148);
        cfg.blockDim = dim3(256);
        cfg.dynamicSmemBytes = SMEM_BYTES;
        cfg.stream = 0;
        cudaLaunchAttribute attrs[1];
        attrs[0].id = cudaLaunchAttributeProgrammaticStreamSerialization;
        attrs[0].val.programmaticStreamSerializationAllowed = 1;
        cfg.attrs = attrs;
        cfg.numAttrs = 1;
        cudaLaunchKernelEx(&cfg, k_simsum);
    }

    // k_lse_final with PDL
    {
        cudaLaunchConfig_t cfg = {};
        cfg.gridDim = dim3(128);
        cfg.blockDim = dim3(128);
        cfg.dynamicSmemBytes = 0;
        cfg.stream = 0;
        cudaLaunchAttribute attrs[1];
        attrs[0].id = cudaLaunchAttributeProgrammaticStreamSerialization;
        attrs[0].val.programmaticStreamSerializationAllowed = 1;
        cfg.attrs = attrs;
        cfg.numAttrs = 1;
        cudaLaunchKernelEx(&cfg, k_lse_final, out);
    }
}